// round 14
// baseline (speedup 1.0000x reference)
#include <cuda_runtime.h>
#include <cuda_bf16.h>

// FilterLayer: y[b,c,h,w] = sum_{di,dj in 5x5} f[b, di*5+dj, h, w] * xpad[b, c, h+di, w+dj]
// x: [4,3,512,512] f32, f: [4,25,512,512] f32, out: [4,3,512,512] f32, zero pad p=2.
//
// R13 = R2 (best steady-state: 4px/thread, 32x8 block, __ldcg f / __ldca x,
// 64 regs, occ 4) restructured for SINGLE-WAVE execution: 512 blocks (< 592
// resident slots), each block processes 2 consecutive h-tiles sequentially.
// Removes the 73%-full second wave + wave-transition bubble that kept DRAM
// idle ~10-15% of elapsed time in R2.

#define WIN 5
#define CH 3

__global__ __launch_bounds__(256, 4)
void FilterLayer_4664334483556_kernel(const float* __restrict__ x,
                                      const float* __restrict__ f,
                                      float* __restrict__ out)
{
    const int H = 512, W = 512;
    const int tx = threadIdx.x;              // 0..31
    const int ty = threadIdx.y;              // 0..7
    const int b  = blockIdx.z;
    const int wb = blockIdx.x * 128 + tx * 4;

    const bool leftOK  = (wb >= 4);
    const bool rightOK = (wb <= W - 8);

    const size_t HW = (size_t)H * W;
    const float* fB = f + ((size_t)b * (WIN * WIN)) * HW + wb;
    const float* xB = x + (size_t)b * CH * HW + wb;
    float*       oB = out + (size_t)b * CH * HW + wb;

    #pragma unroll
    for (int t = 0; t < 2; t++) {
        const int h = (blockIdx.y * 2 + t) * 8 + ty;   // output row for this tile

        float acc[CH][4];
        #pragma unroll
        for (int c = 0; c < CH; c++)
            #pragma unroll
            for (int q = 0; q < 4; q++)
                acc[c][q] = 0.0f;

        const float* fbase = fB + (size_t)h * W;

        #pragma unroll
        for (int di = 0; di < WIN; di++) {
            const int gh = h + di - 2;
            const bool rv = ((unsigned)gh < (unsigned)H);

            // ---- filter row: 5 x LDG.128 via L2 (streaming, zero reuse) ----
            float4 fv[WIN];
            #pragma unroll
            for (int dj = 0; dj < WIN; dj++)
                fv[dj] = __ldcg(reinterpret_cast<const float4*>(
                             fbase + (size_t)(di * WIN + dj) * HW));

            #pragma unroll
            for (int c = 0; c < CH; c++) {
                const float* row = xB + ((size_t)c * H + gh) * W;

                float4 v0 = make_float4(0.f, 0.f, 0.f, 0.f);
                float4 v1 = make_float4(0.f, 0.f, 0.f, 0.f);
                float4 v2 = make_float4(0.f, 0.f, 0.f, 0.f);
                if (rv) {
                    if (leftOK)  v0 = __ldca(reinterpret_cast<const float4*>(row - 4));
                                 v1 = __ldca(reinterpret_cast<const float4*>(row));
                    if (rightOK) v2 = __ldca(reinterpret_cast<const float4*>(row + 4));
                }

                float xr[8];
                xr[0] = v0.z; xr[1] = v0.w;
                xr[2] = v1.x; xr[3] = v1.y; xr[4] = v1.z; xr[5] = v1.w;
                xr[6] = v2.x; xr[7] = v2.y;

                #pragma unroll
                for (int dj = 0; dj < WIN; dj++) {
                    acc[c][0] = fmaf(fv[dj].x, xr[dj + 0], acc[c][0]);
                    acc[c][1] = fmaf(fv[dj].y, xr[dj + 1], acc[c][1]);
                    acc[c][2] = fmaf(fv[dj].z, xr[dj + 2], acc[c][2]);
                    acc[c][3] = fmaf(fv[dj].w, xr[dj + 3], acc[c][3]);
                }
            }
        }

        float* ob = oB + (size_t)h * W;
        #pragma unroll
        for (int c = 0; c < CH; c++) {
            float4 v = make_float4(acc[c][0], acc[c][1], acc[c][2], acc[c][3]);
            *reinterpret_cast<float4*>(ob + c * HW) = v;
        }
    }
}

extern "C" void kernel_launch(void* const* d_in, const int* in_sizes, int n_in,
                              void* d_out, int out_size)
{
    const float* x = (const float*)d_in[0];
    const float* f = (const float*)d_in[1];
    float* out = (float*)d_out;

    dim3 block(32, 8, 1);
    dim3 grid(4, 32, 4);   // 512 blocks -> single wave (<= 592 resident slots)
    FilterLayer_4664334483556_kernel<<<grid, block>>>(x, f, out);
}

// round 16
// speedup vs baseline: 1.1495x; 1.1495x over previous
#include <cuda_runtime.h>
#include <cuda_bf16.h>

// FilterLayer: y[b,c,h,w] = sum_{di,dj in 5x5} f[b, di*5+dj, h, w] * xpad[b, c, h+di, w+dj]
// x: [4,3,512,512] f32, f: [4,25,512,512] f32, out: [4,3,512,512] f32, zero pad p=2.
//
// R14 consolidation: merge of the two best variants (R2: 64 regs / 50% occ
// ceiling; R3: 128-thr blocks for fine wave-granularity work-steal refill).
//  - 4 px/thread, 32x4 blocks, 2048 blocks, launch_bounds(128,8) -> 64 regs,
//    up to 8 blocks (32 warps)/SM.
//  - f: __ldcg LDG.128 (L2 path, zero reuse) -- proven best.
//  - x: __ldca (L1/L2 resident, 25x reuse).
//  - out: __stcs streaming store (evict-first; keeps x L2-resident).
// Steady state is pinned at ~5.0-5.4 TB/s DRAM for this mix (9 experiments);
// this round trims L2 pollution + wave-transition granularity only.

#define WIN 5
#define CH 3

__global__ __launch_bounds__(128, 8)
void FilterLayer_4664334483556_kernel(const float* __restrict__ x,
                                      const float* __restrict__ f,
                                      float* __restrict__ out)
{
    const int H = 512, W = 512;
    const int tx = threadIdx.x;               // 0..31
    const int ty = threadIdx.y;               // 0..3
    const int b  = blockIdx.z;
    const int h  = blockIdx.y * 4 + ty;       // output row
    const int wb = blockIdx.x * 128 + tx * 4; // first of 4 output cols

    const bool leftOK  = (wb >= 4);
    const bool rightOK = (wb <= W - 8);

    float acc[CH][4];
    #pragma unroll
    for (int c = 0; c < CH; c++)
        #pragma unroll
        for (int q = 0; q < 4; q++)
            acc[c][q] = 0.0f;

    const size_t HW = (size_t)H * W;
    const float* fbase = f + ((size_t)b * (WIN * WIN)) * HW + (size_t)h * W + wb;
    const float* xbase = x + (size_t)b * CH * HW + wb;

    #pragma unroll
    for (int di = 0; di < WIN; di++) {
        const int gh = h + di - 2;
        const bool rv = ((unsigned)gh < (unsigned)H);

        // ---- filter row: 5 x LDG.128 via L2 (streaming, zero reuse) ----
        float4 fv[WIN];
        #pragma unroll
        for (int dj = 0; dj < WIN; dj++)
            fv[dj] = __ldcg(reinterpret_cast<const float4*>(
                         fbase + (size_t)(di * WIN + dj) * HW));

        #pragma unroll
        for (int c = 0; c < CH; c++) {
            const float* row = xbase + ((size_t)c * H + gh) * W;

            float4 v0 = make_float4(0.f, 0.f, 0.f, 0.f);
            float4 v1 = make_float4(0.f, 0.f, 0.f, 0.f);
            float4 v2 = make_float4(0.f, 0.f, 0.f, 0.f);
            if (rv) {
                if (leftOK)  v0 = __ldca(reinterpret_cast<const float4*>(row - 4));
                             v1 = __ldca(reinterpret_cast<const float4*>(row));
                if (rightOK) v2 = __ldca(reinterpret_cast<const float4*>(row + 4));
            }

            float xr[8];
            xr[0] = v0.z; xr[1] = v0.w;
            xr[2] = v1.x; xr[3] = v1.y; xr[4] = v1.z; xr[5] = v1.w;
            xr[6] = v2.x; xr[7] = v2.y;

            #pragma unroll
            for (int dj = 0; dj < WIN; dj++) {
                acc[c][0] = fmaf(fv[dj].x, xr[dj + 0], acc[c][0]);
                acc[c][1] = fmaf(fv[dj].y, xr[dj + 1], acc[c][1]);
                acc[c][2] = fmaf(fv[dj].z, xr[dj + 2], acc[c][2]);
                acc[c][3] = fmaf(fv[dj].w, xr[dj + 3], acc[c][3]);
            }
        }
    }

    float* ob = out + (size_t)b * CH * HW + (size_t)h * W + wb;
    #pragma unroll
    for (int c = 0; c < CH; c++) {
        float4 v = make_float4(acc[c][0], acc[c][1], acc[c][2], acc[c][3]);
        __stcs(reinterpret_cast<float4*>(ob + c * HW), v);
    }
}

extern "C" void kernel_launch(void* const* d_in, const int* in_sizes, int n_in,
                              void* d_out, int out_size)
{
    const float* x = (const float*)d_in[0];
    const float* f = (const float*)d_in[1];
    float* out = (float*)d_out;

    dim3 block(32, 4, 1);
    dim3 grid(4, 128, 4);   // (512/128, 512/4, 4) = 2048 blocks
    FilterLayer_4664334483556_kernel<<<grid, block>>>(x, f, out);
}